// round 3
// baseline (speedup 1.0000x reference)
#include <cuda_runtime.h>
#include <math.h>

#define EDGES 65536
#define GRID  2048
#define EPB   (EDGES / GRID)   // 32 edges per block
#define W3J_TOTAL 1875
#define OUT_ALL_OFF ((size_t)EDGES * 9 * 128)   // 75497472

// ---- key tables: (la, lb, lo) for the 23 distinct W3J tensors, in weight-path order ----
__constant__ int KEY_LA[23]  = {0,1,2,3, 0,1,1,2,2,3, 0,1,1,2,2,3,3, 0,1,2,2,3,3};
__constant__ int KEY_LB[23]  = {0,1,2,3, 1,0,2,1,3,2, 2,1,3,0,2,1,3, 3,2,1,3,0,2};
__constant__ int KEY_LO[23]  = {0,0,0,0, 1,1,1,1,1,1, 2,2,2,2,2,2,2, 3,3,3,3,3,3};
__constant__ int W3J_OFF[23] = {0,1,10,35, 84,93,102,147,192,297,
                                402,427,472,577,602,727,832,
                                1077,1126,1231,1336,1581,1630};

__device__ float g_w3j[W3J_TOTAL];

// ================= init: compute real Wigner-3j tensors on device =================
struct C2 { double re, im; };
__device__ __forceinline__ C2 cmul(C2 a, C2 b) {
    return C2{a.re * b.re - a.im * b.im, a.re * b.im + a.im * b.re};
}
__device__ __forceinline__ C2 cconj(C2 a) { return C2{a.re, -a.im}; }
__device__ __forceinline__ C2 cscale(C2 a, double s) { return C2{a.re * s, a.im * s}; }

__device__ __forceinline__ double dfact(int n) {
    const double tab[11] = {1.,1.,2.,6.,24.,120.,720.,5040.,40320.,362880.,3628800.};
    return tab[n];
}

__device__ double su2_cg(int j1, int m1, int j2, int m2, int j3, int m3) {
    if (m3 != m1 + m2) return 0.0;
    double pref = sqrt((2.0 * j3 + 1.0) * dfact(j3 + j1 - j2) * dfact(j3 - j1 + j2) *
                       dfact(j1 + j2 - j3) / dfact(j1 + j2 + j3 + 1));
    pref *= sqrt(dfact(j3 + m3) * dfact(j3 - m3) * dfact(j1 - m1) * dfact(j1 + m1) *
                 dfact(j2 - m2) * dfact(j2 + m2));
    int kmin = max(0, max(j2 - j3 - m1, j1 - j3 + m2));
    int kmax = min(j1 + j2 - j3, min(j1 - m1, j2 + m2));
    double s = 0.0;
    for (int k = kmin; k <= kmax; k++) {
        double term = 1.0 / (dfact(k) * dfact(j1 + j2 - j3 - k) * dfact(j1 - m1 - k) *
                             dfact(j2 + m2 - k) * dfact(j3 - j2 + m1 + k) * dfact(j3 - j1 - m2 + k));
        s += (k & 1) ? -term : term;
    }
    return pref * s;
}

// (-i)^l
__device__ __forceinline__ C2 negi_pow(int l) {
    switch (l & 3) {
        case 0: return C2{1.0, 0.0};
        case 1: return C2{0.0, -1.0};
        case 2: return C2{-1.0, 0.0};
        default: return C2{0.0, 1.0};
    }
}

// Nonzero entries of column c of Q_l (real->complex basis), <=2 entries.
__device__ int q_col_entries(int l, int c, int* rows, C2* vals) {
    C2 pref = negi_pow(l);
    const double s = 0.70710678118654752440;
    int mu = c - l;
    if (mu == 0) { rows[0] = l; vals[0] = pref; return 1; }
    if (mu > 0) {
        rows[0] = l - mu; vals[0] = cscale(pref, s);
        double sgn = (mu & 1) ? -1.0 : 1.0;
        rows[1] = l + mu; vals[1] = cscale(pref, sgn * s);
        return 2;
    }
    int a = -mu;
    rows[0] = l - a; vals[0] = cmul(pref, C2{0.0, -s});
    double sgn = (a & 1) ? -1.0 : 1.0;
    rows[1] = l + a; vals[1] = cmul(pref, C2{0.0, sgn * s});
    return 2;
}

// Nonzero entries of row r of Q_l, <=2 entries (raw, not conjugated).
__device__ int q_row_entries(int l, int r, int* cols, C2* vals) {
    C2 pref = negi_pow(l);
    const double s = 0.70710678118654752440;
    int mu = r - l;
    if (mu == 0) { cols[0] = l; vals[0] = pref; return 1; }
    if (mu < 0) {
        int a = -mu;
        cols[0] = l + a; vals[0] = cscale(pref, s);
        cols[1] = l - a; vals[1] = cmul(pref, C2{0.0, -s});
        return 2;
    }
    double sgn = (mu & 1) ? -1.0 : 1.0;
    cols[0] = l + mu; vals[0] = cscale(pref, sgn * s);
    cols[1] = l - mu; vals[1] = cmul(pref, C2{0.0, sgn * s});
    return 2;
}

__global__ void w3j_init_kernel() {
    __shared__ double sC[343];
    __shared__ double sCr[245];
    __shared__ double sred[256];
    int key = blockIdx.x;
    int la = KEY_LA[key], lb = KEY_LB[key], lo = KEY_LO[key];
    int na = 2 * la + 1, nb = 2 * lb + 1, no = 2 * lo + 1;
    int n = na * nb * no;
    int t = threadIdx.x;

    // dense real-CG tensor C[i,k,m]
    for (int idx = t; idx < n; idx += blockDim.x) {
        int i = idx / (nb * no);
        int rem = idx % (nb * no);
        int k = rem / no;
        int m = rem % no;
        int m1 = i - la, m2 = k - lb, m3 = m - lo;
        sC[idx] = (m3 == m1 + m2) ? su2_cg(la, m1, lb, m2, lo, m3) : 0.0;
    }
    __syncthreads();

    // change of basis: Cr[ja,jb,n] = Re( sum Q1[i,ja] Q2[k,jb] conj(Q3)[n,m] C[i,k,m] )
    double local_sq = 0.0;
    for (int idx = t; idx < n; idx += blockDim.x) {
        int ja = idx / (nb * no);
        int rem = idx % (nb * no);
        int jb = rem / no;
        int jn = rem % no;
        int r1[2]; C2 v1[2]; int n1 = q_col_entries(la, ja, r1, v1);
        int r2[2]; C2 v2[2]; int n2 = q_col_entries(lb, jb, r2, v2);
        int c3[2]; C2 v3[2]; int n3 = q_row_entries(lo, jn, c3, v3);
        C2 acc{0.0, 0.0};
        for (int a = 0; a < n1; a++)
            for (int b = 0; b < n2; b++)
                for (int c = 0; c < n3; c++) {
                    C2 q = cmul(cmul(v1[a], v2[b]), cconj(v3[c]));
                    double cv = sC[(r1[a] * nb + r2[b]) * no + c3[c]];
                    acc.re += q.re * cv;
                    acc.im += q.im * cv;
                }
        sCr[idx] = acc.re;
        local_sq += acc.re * acc.re;
    }
    sred[t] = local_sq;
    __syncthreads();
    for (int s = 128; s > 0; s >>= 1) {
        if (t < s) sred[t] += sred[t + s];
        __syncthreads();
    }
    double inv = 1.0 / sqrt(sred[0]);
    for (int idx = t; idx < n; idx += blockDim.x)
        g_w3j[W3J_OFF[key] + idx] = (float)(sCr[idx] * inv);
}

// ================= main kernel =================
__device__ __forceinline__ float fsig(float v) { return 1.0f / (1.0f + __expf(-v)); }

__global__ void __launch_bounds__(128)
cg_main_kernel(const float* __restrict__ x, const float* __restrict__ y,
               const float* __restrict__ wcg, const float* __restrict__ bcg,
               const float* __restrict__ wall, const float* __restrict__ ball,
               float* __restrict__ out) {
    __shared__ float sW3J[W3J_TOTAL];
    __shared__ float sWcg[3200];
    __shared__ float sBcg[384];
    __shared__ float sWall[35];
    __shared__ float sBall[4];
    __shared__ float sxy[32];
    __shared__ float sz[99];

    int t = threadIdx.x;
    for (int i = t; i < W3J_TOTAL; i += 128) sW3J[i] = g_w3j[i];
    for (int i = t; i < 3200; i += 128) sWcg[i] = wcg[i];
    for (int i = t; i < 384; i += 128) sBcg[i] = bcg[i];
    if (t < 35) sWall[t] = wall[t];
    if (t < 4) sBall[t] = ball[t];

    int e0 = blockIdx.x * EPB;
    float pre = 0.0f;
    if (t < 32)
        pre = (t < 16) ? x[(size_t)e0 * 16 + t] : y[(size_t)e0 * 16 + (t - 16)];

    // z-component decode for this thread (computed once)
    int zkey = 0, zk = 0;
    if (t < 4) { zkey = t; zk = 0; }
    else if (t < 22) { int q = t - 4; zkey = 4 + q / 3; zk = q % 3; }
    else if (t < 57) { int q = t - 22; zkey = 10 + q / 5; zk = q % 5; }
    else if (t < 99) { int q = t - 57; zkey = 17 + q / 7; zk = q % 7; }
    int zla = KEY_LA[zkey], zlb = KEY_LB[zkey];
    int zna = 2 * zla + 1, znb = 2 * zlb + 1, zno = 2 * KEY_LO[zkey] + 1;
    int zw3joff = W3J_OFF[zkey];
    int zxoff = zla * zla, zyoff = 16 + zlb * zlb;

    for (int ei = 0; ei < EPB; ++ei) {
        int e = e0 + ei;
        if (t < 32) sxy[t] = pre;
        __syncthreads();
        // prefetch next edge's x/y while we compute
        if (t < 32 && ei + 1 < EPB) {
            int en = e + 1;
            pre = (t < 16) ? x[(size_t)en * 16 + t] : y[(size_t)en * 16 + (t - 16)];
        }
        // ---- phase 1: shared z components ----
        if (t < 99) {
            const float* w = &sW3J[zw3joff];
            const float* xs = &sxy[zxoff];
            const float* ys = &sxy[zyoff];
            float acc = 0.0f;
            for (int i = 0; i < zna; i++) {
                float xv = xs[i];
                for (int j = 0; j < znb; j++)
                    acc += xv * ys[j] * w[(i * znb + j) * zno + zk];
            }
            sz[t] = acc;
        }
        __syncthreads();

        // ---- phase 2: per-channel outputs (t = channel) ----
        float z0a = sz[0], z0b = sz[1], z0c = sz[2], z0d = sz[3];
        // entry 0: (128, lo=0): silu
        float v0 = z0a * sWcg[t] + z0b * sWcg[128 + t] + z0c * sWcg[256 + t] + z0d * sWcg[384 + t];
        v0 = 0.5f * v0 + sBcg[t];
        float scv = v0 * fsig(v0);
        // entry 1: (256, lo=0): two gates per thread
        float g0 = z0a * sWcg[512 + t] + z0b * sWcg[768 + t] + z0c * sWcg[1024 + t] + z0d * sWcg[1280 + t];
        g0 = fsig(0.5f * g0 + sBcg[128 + t]);
        float g1 = z0a * sWcg[640 + t] + z0b * sWcg[896 + t] + z0c * sWcg[1152 + t] + z0d * sWcg[1408 + t];
        g1 = fsig(0.5f * g1 + sBcg[256 + t]);
        // entry 2: (128, lo=1): 6 paths
        float u0 = 0.f, u1 = 0.f, u2 = 0.f;
#pragma unroll
        for (int p = 0; p < 6; p++) {
            float wv = sWcg[1536 + p * 128 + t];
            u0 += sz[4 + p * 3 + 0] * wv;
            u1 += sz[4 + p * 3 + 1] * wv;
            u2 += sz[4 + p * 3 + 2] * wv;
        }
        // entry 3: (128, lo=2): 7 paths
        float w0 = 0.f, w1 = 0.f, w2 = 0.f, w3 = 0.f, w4 = 0.f;
#pragma unroll
        for (int p = 0; p < 7; p++) {
            float wv = sWcg[2304 + p * 128 + t];
            w0 += sz[22 + p * 5 + 0] * wv;
            w1 += sz[22 + p * 5 + 1] * wv;
            w2 += sz[22 + p * 5 + 2] * wv;
            w3 += sz[22 + p * 5 + 3] * wv;
            w4 += sz[22 + p * 5 + 4] * wv;
        }
        const float S1 = 0.70710678118654752f;   // sqrt(3/6)
        const float S2 = 0.84515425472851657f;   // sqrt(5/7)
        size_t base = ((size_t)e * 9) * 128 + t;
        out[base] = scv;
        float gg = S1 * g0;
        out[base + 128] = u0 * gg;
        out[base + 256] = u1 * gg;
        out[base + 384] = u2 * gg;
        float hh = S2 * g1;
        out[base + 512] = w0 * hh;
        out[base + 640] = w1 * hh;
        out[base + 768] = w2 * hh;
        out[base + 896] = w3 * hh;
        out[base + 1024] = w4 * hh;

        // ---- "all" branch: 16 outputs, one per thread ----
        if (t < 16) {
            float* oa = out + OUT_ALL_OFF + (size_t)e * 16;
            if (t == 0) {
                float v = 0.5f * (z0a * sWall[0] + z0b * sWall[1] + z0c * sWall[2] + z0d * sWall[3]) + sBall[0];
                oa[0] = v * fsig(v);
            } else if (t < 4) {
                int k = t - 1;
                float g = fsig(0.5f * (z0a * sWall[4] + z0b * sWall[7] + z0c * sWall[10] + z0d * sWall[13]) + sBall[1]);
                float u = 0.f;
#pragma unroll
                for (int p = 0; p < 6; p++) u += sz[4 + 3 * p + k] * sWall[16 + p];
                oa[t] = 0.70710678118654752f * u * g;
            } else if (t < 9) {
                int k = t - 4;
                float g = fsig(0.5f * (z0a * sWall[5] + z0b * sWall[8] + z0c * sWall[11] + z0d * sWall[14]) + sBall[2]);
                float u = 0.f;
#pragma unroll
                for (int p = 0; p < 7; p++) u += sz[22 + 5 * p + k] * sWall[22 + p];
                oa[t] = 0.84515425472851657f * u * g;
            } else {
                int k = t - 9;
                float g = fsig(0.5f * (z0a * sWall[6] + z0b * sWall[9] + z0c * sWall[12] + z0d * sWall[15]) + sBall[3]);
                float u = 0.f;
#pragma unroll
                for (int p = 0; p < 6; p++) u += sz[57 + 7 * p + k] * sWall[29 + p];
                oa[t] = 1.08012344973464367f * u * g;   // sqrt(7/6)
            }
        }
        __syncthreads();   // protect sxy/sz before next iteration overwrites
    }
}

extern "C" void kernel_launch(void* const* d_in, const int* in_sizes, int n_in,
                              void* d_out, int out_size) {
    const float* x    = (const float*)d_in[0];
    const float* y    = (const float*)d_in[1];
    const float* wcg  = (const float*)d_in[2];
    const float* bcg  = (const float*)d_in[3];
    const float* wall = (const float*)d_in[4];
    const float* ball = (const float*)d_in[5];
    float* out = (float*)d_out;

    w3j_init_kernel<<<23, 256>>>();
    cg_main_kernel<<<GRID, 128>>>(x, y, wcg, bcg, wall, ball, out);
}

// round 4
// speedup vs baseline: 1.3731x; 1.3731x over previous
#include <cuda_runtime.h>
#include <math.h>

#define EDGES 65536
#define GRID  2048
#define EPB   (EDGES / GRID)   // 32 edges per block
#define W3J_TOTAL 1875
#define NZ_MAX 1875
#define OUT_ALL_OFF ((size_t)EDGES * 9 * 128)   // 75497472

// ---- key tables: (la, lb, lo) for the 23 distinct W3J tensors, in weight-path order ----
__constant__ int KEY_LA[23]  = {0,1,2,3, 0,1,1,2,2,3, 0,1,1,2,2,3,3, 0,1,2,2,3,3};
__constant__ int KEY_LB[23]  = {0,1,2,3, 1,0,2,1,3,2, 2,1,3,0,2,1,3, 3,2,1,3,0,2};
__constant__ int KEY_LO[23]  = {0,0,0,0, 1,1,1,1,1,1, 2,2,2,2,2,2,2, 3,3,3,3,3,3};
__constant__ int W3J_OFF[23] = {0,1,10,35, 84,93,102,147,192,297,
                                402,427,472,577,602,727,832,
                                1077,1126,1231,1336,1581,1630};

__device__ float g_w3j[W3J_TOTAL];
__device__ float2 g_nz[NZ_MAX];
__device__ int g_cnt[99];
__device__ int g_off[99];
__device__ int g_total;

// ================= init: compute real Wigner-3j tensors on device =================
struct C2 { double re, im; };
__device__ __forceinline__ C2 cmul(C2 a, C2 b) {
    return C2{a.re * b.re - a.im * b.im, a.re * b.im + a.im * b.re};
}
__device__ __forceinline__ C2 cconj(C2 a) { return C2{a.re, -a.im}; }
__device__ __forceinline__ C2 cscale(C2 a, double s) { return C2{a.re * s, a.im * s}; }

__device__ __forceinline__ double dfact(int n) {
    const double tab[11] = {1.,1.,2.,6.,24.,120.,720.,5040.,40320.,362880.,3628800.};
    return tab[n];
}

__device__ double su2_cg(int j1, int m1, int j2, int m2, int j3, int m3) {
    if (m3 != m1 + m2) return 0.0;
    double pref = sqrt((2.0 * j3 + 1.0) * dfact(j3 + j1 - j2) * dfact(j3 - j1 + j2) *
                       dfact(j1 + j2 - j3) / dfact(j1 + j2 + j3 + 1));
    pref *= sqrt(dfact(j3 + m3) * dfact(j3 - m3) * dfact(j1 - m1) * dfact(j1 + m1) *
                 dfact(j2 - m2) * dfact(j2 + m2));
    int kmin = max(0, max(j2 - j3 - m1, j1 - j3 + m2));
    int kmax = min(j1 + j2 - j3, min(j1 - m1, j2 + m2));
    double s = 0.0;
    for (int k = kmin; k <= kmax; k++) {
        double term = 1.0 / (dfact(k) * dfact(j1 + j2 - j3 - k) * dfact(j1 - m1 - k) *
                             dfact(j2 + m2 - k) * dfact(j3 - j2 + m1 + k) * dfact(j3 - j1 - m2 + k));
        s += (k & 1) ? -term : term;
    }
    return pref * s;
}

__device__ __forceinline__ C2 negi_pow(int l) {
    switch (l & 3) {
        case 0: return C2{1.0, 0.0};
        case 1: return C2{0.0, -1.0};
        case 2: return C2{-1.0, 0.0};
        default: return C2{0.0, 1.0};
    }
}

__device__ int q_col_entries(int l, int c, int* rows, C2* vals) {
    C2 pref = negi_pow(l);
    const double s = 0.70710678118654752440;
    int mu = c - l;
    if (mu == 0) { rows[0] = l; vals[0] = pref; return 1; }
    if (mu > 0) {
        rows[0] = l - mu; vals[0] = cscale(pref, s);
        double sgn = (mu & 1) ? -1.0 : 1.0;
        rows[1] = l + mu; vals[1] = cscale(pref, sgn * s);
        return 2;
    }
    int a = -mu;
    rows[0] = l - a; vals[0] = cmul(pref, C2{0.0, -s});
    double sgn = (a & 1) ? -1.0 : 1.0;
    rows[1] = l + a; vals[1] = cmul(pref, C2{0.0, sgn * s});
    return 2;
}

__device__ int q_row_entries(int l, int r, int* cols, C2* vals) {
    C2 pref = negi_pow(l);
    const double s = 0.70710678118654752440;
    int mu = r - l;
    if (mu == 0) { cols[0] = l; vals[0] = pref; return 1; }
    if (mu < 0) {
        int a = -mu;
        cols[0] = l + a; vals[0] = cscale(pref, s);
        cols[1] = l - a; vals[1] = cmul(pref, C2{0.0, -s});
        return 2;
    }
    double sgn = (mu & 1) ? -1.0 : 1.0;
    cols[0] = l + mu; vals[0] = cscale(pref, sgn * s);
    cols[1] = l - mu; vals[1] = cmul(pref, C2{0.0, sgn * s});
    return 2;
}

__global__ void w3j_init_kernel() {
    __shared__ double sC[343];
    __shared__ double sCr[245];
    __shared__ double sred[256];
    int key = blockIdx.x;
    int la = KEY_LA[key], lb = KEY_LB[key], lo = KEY_LO[key];
    int na = 2 * la + 1, nb = 2 * lb + 1, no = 2 * lo + 1;
    int n = na * nb * no;
    int t = threadIdx.x;

    for (int idx = t; idx < n; idx += blockDim.x) {
        int i = idx / (nb * no);
        int rem = idx % (nb * no);
        int k = rem / no;
        int m = rem % no;
        int m1 = i - la, m2 = k - lb, m3 = m - lo;
        sC[idx] = (m3 == m1 + m2) ? su2_cg(la, m1, lb, m2, lo, m3) : 0.0;
    }
    __syncthreads();

    double local_sq = 0.0;
    for (int idx = t; idx < n; idx += blockDim.x) {
        int ja = idx / (nb * no);
        int rem = idx % (nb * no);
        int jb = rem / no;
        int jn = rem % no;
        int r1[2]; C2 v1[2]; int n1 = q_col_entries(la, ja, r1, v1);
        int r2[2]; C2 v2[2]; int n2 = q_col_entries(lb, jb, r2, v2);
        int c3[2]; C2 v3[2]; int n3 = q_row_entries(lo, jn, c3, v3);
        C2 acc{0.0, 0.0};
        for (int a = 0; a < n1; a++)
            for (int b = 0; b < n2; b++)
                for (int c = 0; c < n3; c++) {
                    C2 q = cmul(cmul(v1[a], v2[b]), cconj(v3[c]));
                    double cv = sC[(r1[a] * nb + r2[b]) * no + c3[c]];
                    acc.re += q.re * cv;
                    acc.im += q.im * cv;
                }
        sCr[idx] = acc.re;
        local_sq += acc.re * acc.re;
    }
    sred[t] = local_sq;
    __syncthreads();
    for (int s = 128; s > 0; s >>= 1) {
        if (t < s) sred[t] += sred[t + s];
        __syncthreads();
    }
    double inv = 1.0 / sqrt(sred[0]);
    for (int idx = t; idx < n; idx += blockDim.x)
        g_w3j[W3J_OFF[key] + idx] = (float)(sCr[idx] * inv);
}

// slot (0..98) -> (key, k-within-output)
__device__ __forceinline__ void slot_decode(int t, int& key, int& k) {
    if (t < 4) { key = t; k = 0; }
    else if (t < 22) { int q = t - 4; key = 4 + q / 3; k = q % 3; }
    else if (t < 57) { int q = t - 22; key = 10 + q / 5; k = q % 5; }
    else { int q = t - 57; key = 17 + q / 7; k = q % 7; }
}

// ========== compress: per-z-slot nonzero list (coeff, product-index) ==========
__global__ void w3j_compress_kernel() {
    __shared__ int scnt[99];
    __shared__ int soff[99];
    int t = threadIdx.x;
    int key = 0, k = 0;
    bool valid = (t < 99);
    if (valid) slot_decode(t, key, k);
    int la = KEY_LA[key], lb = KEY_LB[key], lo = KEY_LO[key];
    int na = 2 * la + 1, nb = 2 * lb + 1, no = 2 * lo + 1;
    int woff = W3J_OFF[key];
    int cnt = 0;
    if (valid) {
        for (int i = 0; i < na; i++)
            for (int j = 0; j < nb; j++)
                if (fabsf(g_w3j[woff + (i * nb + j) * no + k]) > 1e-10f) cnt++;
        scnt[t] = cnt;
    }
    __syncthreads();
    if (t == 0) {
        int acc = 0;
        for (int i = 0; i < 99; i++) { soff[i] = acc; acc += scnt[i]; }
        g_total = acc;
    }
    __syncthreads();
    if (valid) {
        g_cnt[t] = cnt;
        int w = soff[t];
        g_off[t] = w;
        for (int i = 0; i < na; i++)
            for (int j = 0; j < nb; j++) {
                float c = g_w3j[woff + (i * nb + j) * no + k];
                if (fabsf(c) > 1e-10f) {
                    int pidx = (la * la + i) * 16 + (lb * lb + j);  // index into 16x16 product table
                    g_nz[w++] = make_float2(c, __int_as_float(pidx));
                }
            }
    }
}

// ================= main kernel =================
__device__ __forceinline__ float fsig(float v) { return 1.0f / (1.0f + __expf(-v)); }

__global__ void __launch_bounds__(128)
cg_main_kernel(const float* __restrict__ x, const float* __restrict__ y,
               const float* __restrict__ wcg, const float* __restrict__ bcg,
               const float* __restrict__ wall, const float* __restrict__ ball,
               float* __restrict__ out) {
    __shared__ float2 snz[NZ_MAX];
    __shared__ float sProd[256];
    __shared__ __align__(16) float sz0[4];
    __shared__ __align__(16) float szA[20];   // slots 4..21 (18 used)
    __shared__ __align__(16) float szB[36];   // slots 22..56 (35 used)
    __shared__ __align__(16) float szD[44];   // slots 57..98 (42 used)
    __shared__ float sWall[35];
    __shared__ float sBall[4];

    int t = threadIdx.x;
    int total = g_total;
    for (int i = t; i < total; i += 128) snz[i] = g_nz[i];
    if (t < 35) sWall[t] = wall[t];
    if (t < 4) sBall[t] = ball[t];

    // per-thread z-slot setup
    int myoff = 0, mycnt = 0;
    float* zdst = &sz0[0];
    if (t < 99) {
        myoff = g_off[t];
        mycnt = g_cnt[t];
        if (t < 4) zdst = &sz0[t];
        else if (t < 22) zdst = &szA[t - 4];
        else if (t < 57) zdst = &szB[t - 22];
        else zdst = &szD[t - 57];
    }

    // per-channel weights hoisted to registers (fixed for all edges)
    float w00 = wcg[t], w01 = wcg[128 + t], w02 = wcg[256 + t], w03 = wcg[384 + t];
    float a0w = wcg[512 + t], a1w = wcg[768 + t], a2w = wcg[1024 + t], a3w = wcg[1280 + t];
    float c0w = wcg[640 + t], c1w = wcg[896 + t], c2w = wcg[1152 + t], c3w = wcg[1408 + t];
    float uw0 = wcg[1536 + t], uw1 = wcg[1664 + t], uw2 = wcg[1792 + t];
    float uw3 = wcg[1920 + t], uw4 = wcg[2048 + t], uw5 = wcg[2176 + t];
    float vw0 = wcg[2304 + t], vw1 = wcg[2432 + t], vw2 = wcg[2560 + t], vw3 = wcg[2688 + t];
    float vw4 = wcg[2816 + t], vw5 = wcg[2944 + t], vw6 = wcg[3072 + t];
    float b0 = bcg[t], b1 = bcg[128 + t], b2 = bcg[256 + t];

    int e0 = blockIdx.x * EPB;
    float pre = 0.0f;
    if (t < 32)
        pre = (t < 16) ? x[(size_t)e0 * 16 + t] : y[(size_t)e0 * 16 + (t - 16)];

    for (int ei = 0; ei < EPB; ++ei) {
        int e = e0 + ei;
        // warp 0: build the 16x16 product table via shuffles, then prefetch next edge
        if (t < 32) {
#pragma unroll
            for (int r = 0; r < 8; r++) {
                int p = r * 32 + t;
                float xv = __shfl_sync(0xffffffffu, pre, p >> 4);
                float yv = __shfl_sync(0xffffffffu, pre, 16 + (p & 15));
                sProd[p] = xv * yv;
            }
            if (ei + 1 < EPB) {
                int en = e + 1;
                pre = (t < 16) ? x[(size_t)en * 16 + t] : y[(size_t)en * 16 + (t - 16)];
            }
        }
        __syncthreads();

        // phase 1: sparse z accumulation
        if (t < 99) {
            float acc = 0.0f;
            for (int n = 0; n < mycnt; n++) {
                float2 ent = snz[myoff + n];
                acc = fmaf(ent.x, sProd[__float_as_int(ent.y)], acc);
            }
            *zdst = acc;
        }
        __syncthreads();

        // phase 2: per-channel outputs (t = channel)
        float4 z0 = *(const float4*)sz0;
        float v0 = fmaf(z0.x, w00, fmaf(z0.y, w01, fmaf(z0.z, w02, z0.w * w03)));
        v0 = 0.5f * v0 + b0;
        float scv = v0 * fsig(v0);
        float g0 = fmaf(z0.x, a0w, fmaf(z0.y, a1w, fmaf(z0.z, a2w, z0.w * a3w)));
        g0 = fsig(0.5f * g0 + b1);
        float g1 = fmaf(z0.x, c0w, fmaf(z0.y, c1w, fmaf(z0.z, c2w, z0.w * c3w)));
        g1 = fsig(0.5f * g1 + b2);

        // entry 2 (lo=1): u_k = sum_p szA[3p+k]*uw_p, vectorized LDS
        float u0, u1, u2;
        {
            float4 v;
            v = *(const float4*)&szA[0];
            u0 = v.x * uw0; u1 = v.y * uw0; u2 = v.z * uw0; u0 = fmaf(v.w, uw1, u0);
            v = *(const float4*)&szA[4];
            u1 = fmaf(v.x, uw1, u1); u2 = fmaf(v.y, uw1, u2);
            u0 = fmaf(v.z, uw2, u0); u1 = fmaf(v.w, uw2, u1);
            v = *(const float4*)&szA[8];
            u2 = fmaf(v.x, uw2, u2); u0 = fmaf(v.y, uw3, u0);
            u1 = fmaf(v.z, uw3, u1); u2 = fmaf(v.w, uw3, u2);
            v = *(const float4*)&szA[12];
            u0 = fmaf(v.x, uw4, u0); u1 = fmaf(v.y, uw4, u1);
            u2 = fmaf(v.z, uw4, u2); u0 = fmaf(v.w, uw5, u0);
            float2 v2 = *(const float2*)&szA[16];
            u1 = fmaf(v2.x, uw5, u1); u2 = fmaf(v2.y, uw5, u2);
        }
        // entry 3 (lo=2): q_k = sum_p szB[5p+k]*vw_p
        float q0, q1, q2, q3, q4;
        {
            float4 v;
            v = *(const float4*)&szB[0];
            q0 = v.x * vw0; q1 = v.y * vw0; q2 = v.z * vw0; q3 = v.w * vw0;
            v = *(const float4*)&szB[4];
            q4 = v.x * vw0; q0 = fmaf(v.y, vw1, q0); q1 = fmaf(v.z, vw1, q1); q2 = fmaf(v.w, vw1, q2);
            v = *(const float4*)&szB[8];
            q3 = fmaf(v.x, vw1, q3); q4 = fmaf(v.y, vw1, q4); q0 = fmaf(v.z, vw2, q0); q1 = fmaf(v.w, vw2, q1);
            v = *(const float4*)&szB[12];
            q2 = fmaf(v.x, vw2, q2); q3 = fmaf(v.y, vw2, q3); q4 = fmaf(v.z, vw2, q4); q0 = fmaf(v.w, vw3, q0);
            v = *(const float4*)&szB[16];
            q1 = fmaf(v.x, vw3, q1); q2 = fmaf(v.y, vw3, q2); q3 = fmaf(v.z, vw3, q3); q4 = fmaf(v.w, vw3, q4);
            v = *(const float4*)&szB[20];
            q0 = fmaf(v.x, vw4, q0); q1 = fmaf(v.y, vw4, q1); q2 = fmaf(v.z, vw4, q2); q3 = fmaf(v.w, vw4, q3);
            v = *(const float4*)&szB[24];
            q4 = fmaf(v.x, vw4, q4); q0 = fmaf(v.y, vw5, q0); q1 = fmaf(v.z, vw5, q1); q2 = fmaf(v.w, vw5, q2);
            v = *(const float4*)&szB[28];
            q3 = fmaf(v.x, vw5, q3); q4 = fmaf(v.y, vw5, q4); q0 = fmaf(v.z, vw6, q0); q1 = fmaf(v.w, vw6, q1);
            v = *(const float4*)&szB[32];   // szB[35] is padding (unused lane)
            q2 = fmaf(v.x, vw6, q2); q3 = fmaf(v.y, vw6, q3); q4 = fmaf(v.z, vw6, q4);
        }

        const float S1 = 0.70710678118654752f;   // sqrt(3/6)
        const float S2 = 0.84515425472851657f;   // sqrt(5/7)
        size_t base = ((size_t)e * 9) * 128 + t;
        out[base] = scv;
        float gg = S1 * g0;
        out[base + 128] = u0 * gg;
        out[base + 256] = u1 * gg;
        out[base + 384] = u2 * gg;
        float hh = S2 * g1;
        out[base + 512] = q0 * hh;
        out[base + 640] = q1 * hh;
        out[base + 768] = q2 * hh;
        out[base + 896] = q3 * hh;
        out[base + 1024] = q4 * hh;

        // ---- "all" branch: 16 outputs ----
        if (t < 16) {
            float* oa = out + OUT_ALL_OFF + (size_t)e * 16;
            if (t == 0) {
                float v = 0.5f * (z0.x * sWall[0] + z0.y * sWall[1] + z0.z * sWall[2] + z0.w * sWall[3]) + sBall[0];
                oa[0] = v * fsig(v);
            } else if (t < 4) {
                int k = t - 1;
                float g = fsig(0.5f * (z0.x * sWall[4] + z0.y * sWall[7] + z0.z * sWall[10] + z0.w * sWall[13]) + sBall[1]);
                float u = 0.f;
#pragma unroll
                for (int p = 0; p < 6; p++) u += szA[3 * p + k] * sWall[16 + p];
                oa[t] = 0.70710678118654752f * u * g;
            } else if (t < 9) {
                int k = t - 4;
                float g = fsig(0.5f * (z0.x * sWall[5] + z0.y * sWall[8] + z0.z * sWall[11] + z0.w * sWall[14]) + sBall[2]);
                float u = 0.f;
#pragma unroll
                for (int p = 0; p < 7; p++) u += szB[5 * p + k] * sWall[22 + p];
                oa[t] = 0.84515425472851657f * u * g;
            } else {
                int k = t - 9;
                float g = fsig(0.5f * (z0.x * sWall[6] + z0.y * sWall[9] + z0.z * sWall[12] + z0.w * sWall[15]) + sBall[3]);
                float u = 0.f;
#pragma unroll
                for (int p = 0; p < 6; p++) u += szD[7 * p + k] * sWall[29 + p];
                oa[t] = 1.08012344973464367f * u * g;   // sqrt(7/6)
            }
        }
        __syncthreads();   // protect sProd/sz before next iteration overwrites
    }
}

extern "C" void kernel_launch(void* const* d_in, const int* in_sizes, int n_in,
                              void* d_out, int out_size) {
    const float* x    = (const float*)d_in[0];
    const float* y    = (const float*)d_in[1];
    const float* wcg  = (const float*)d_in[2];
    const float* bcg  = (const float*)d_in[3];
    const float* wall = (const float*)d_in[4];
    const float* ball = (const float*)d_in[5];
    float* out = (float*)d_out;

    w3j_init_kernel<<<23, 256>>>();
    w3j_compress_kernel<<<1, 128>>>();
    cg_main_kernel<<<GRID, 128>>>(x, y, wcg, bcg, wall, ball, out);
}